// round 17
// baseline (speedup 1.0000x reference)
#include <cuda_runtime.h>
#include <cuda_fp16.h>
#include <cstdint>

#define T_STEPS 48
#define B_SZ    512
#define D_SZ    1024
#define H_SZ    1024
#define G4      (4 * H_SZ)
#define BH      (B_SZ * H_SZ)
#define NTILE   128                       // recurrence tiles = consumer CTAs

// ---------------- scratch (static device globals; no allocation) ----------
__device__ float    g_Gpool [B_SZ * G4];                          // 8 MB
__device__ float    g_Gin   [(size_t)(T_STEPS - 1) * B_SZ * G4];  // ~386 MB
__device__ float    g_bias_p[G4];
__device__ uint16_t g_wih_h [(size_t)G4 * 2 * D_SZ];              // 16 MB
__device__ uint16_t g_whh_h [(size_t)G4 * H_SZ];                  // 8 MB
__device__ uint16_t g_dh_h  [(size_t)(T_STEPS - 1) * B_SZ * D_SZ]; // 49 MB
__device__ uint16_t g_pl_h  [B_SZ * D_SZ];                        // 1 MB
__device__ uint16_t g_h_h   [2][BH];                              // ping-pong
__device__ unsigned int g_bar_ctr;                                // h grid barrier
__device__ unsigned int g_gin_flag[T_STEPS * NTILE];              // Gin tile ready

// ===================== helpers =============================================
__device__ __forceinline__ float tanha(float x) {
    float y; asm("tanh.approx.f32 %0, %1;" : "=f"(y) : "f"(x)); return y;
}
__device__ __forceinline__ float siga(float x) {
    return fmaf(tanha(0.5f * x), 0.5f, 0.5f);
}
__device__ __forceinline__ uint32_t smem_u32(const void* p) {
    uint32_t a;
    asm("{ .reg .u64 t; cvta.to.shared.u64 t, %1; cvt.u32.u64 %0, t; }"
        : "=r"(a) : "l"(p));
    return a;
}
__device__ __forceinline__ void cp16(uint32_t dst, const void* src) {
    asm volatile("cp.async.ca.shared.global [%0], [%1], 16;" :: "r"(dst), "l"(src));
}
#define CP_COMMIT() asm volatile("cp.async.commit_group;" ::: "memory")
#define CP_WAIT(n)  asm volatile("cp.async.wait_group %0;" :: "n"(n) : "memory")

__device__ __forceinline__ uint32_t fpack2(float f0, float f1) {
    uint32_t r;
    asm("cvt.rn.f16x2.f32 %0, %1, %2;" : "=r"(r) : "f"(f1), "f"(f0));
    return r;
}

// mma.sync m16n8k16 fp16: D += A*B (row.col), fp32 accumulate
#define MMA_F16(d, a, b)                                                      \
    asm volatile(                                                             \
        "mma.sync.aligned.m16n8k16.row.col.f32.f16.f16.f32 "                  \
        "{%0,%1,%2,%3}, {%4,%5,%6,%7}, {%8,%9}, {%0,%1,%2,%3};"               \
        : "+f"((d)[0]), "+f"((d)[1]), "+f"((d)[2]), "+f"((d)[3])              \
        : "r"((a)[0]), "r"((a)[1]), "r"((a)[2]), "r"((a)[3]),                 \
          "r"((b)[0]), "r"((b)[1]))

#define BK        32
#define ROW_BY    80                      // 64 B data + 16 pad, conflict-free
#define PLANE_BY  (128 * ROW_BY)          // 10240
#define STAGE_BY  (2 * PLANE_BY)          // Ah, Bh = 20480
#define SMEM_B    (2 * STAGE_BY)          // 40960 (2-stage, measured-best)

// mainloop core: 2-stage cp.async pipeline, 64x32 warp tiles (R12 config).
// Expects locals: tid, wm, wn, g, t, acc[4][4][4], pAh, pBh, dbase, smc.
#define GEMM_MAINLOOP(KTOT)                                                   \
    do {                                                                      \
        auto issue_ = [&](int kt, int s) {                                    \
            const size_t ko = (size_t)kt * (BK * 2);                          \
            const uint32_t d0 = dbase + s * STAGE_BY;                         \
            cp16(d0,            pAh + ko);  cp16(d0 + 16,            pAh + ko + 16); \
            cp16(d0 + PLANE_BY, pBh + ko);  cp16(d0 + PLANE_BY + 16, pBh + ko + 16); \
        };                                                                    \
        issue_(0, 0); CP_COMMIT();                                            \
        const int KT_ = (KTOT) / BK;                                          \
        for (int kt = 0; kt < KT_; kt++) {                                    \
            if (kt + 1 < KT_) { issue_(kt + 1, (kt + 1) & 1); CP_COMMIT(); CP_WAIT(1); } \
            else             { CP_WAIT(0); }                                  \
            __syncthreads();                                                  \
            const char* st_  = smc + (kt & 1) * STAGE_BY;                     \
            const char* sAh_ = st_;                                           \
            const char* sBh_ = st_ + PLANE_BY;                                \
            _Pragma("unroll")                                                 \
            for (int ks = 0; ks < 2; ks++) {                                  \
                const int kb = ks * 32 + t * 4;                               \
                uint32_t bh[4][2];                                            \
                _Pragma("unroll")                                             \
                for (int nt = 0; nt < 4; nt++) {                              \
                    const int rowb = (wn * 32 + nt * 8 + g) * ROW_BY + kb;    \
                    bh[nt][0] = *(const uint32_t*)(sBh_ + rowb);              \
                    bh[nt][1] = *(const uint32_t*)(sBh_ + rowb + 16);         \
                }                                                             \
                _Pragma("unroll")                                             \
                for (int mt = 0; mt < 4; mt++) {                              \
                    const int rowb = (wm * 64 + mt * 16 + g) * ROW_BY + kb;   \
                    uint32_t ah[4];                                           \
                    ah[0] = *(const uint32_t*)(sAh_ + rowb);                  \
                    ah[1] = *(const uint32_t*)(sAh_ + rowb + 8 * ROW_BY);     \
                    ah[2] = *(const uint32_t*)(sAh_ + rowb + 16);             \
                    ah[3] = *(const uint32_t*)(sAh_ + rowb + 8 * ROW_BY + 16);\
                    _Pragma("unroll")                                         \
                    for (int nt = 0; nt < 4; nt++) MMA_F16(acc[mt][nt], ah, bh[nt]); \
                }                                                             \
            }                                                                 \
            __syncthreads();                                                  \
        }                                                                     \
    } while (0)

// ===================== standalone GEMM (Gpool prep only) ====================
__global__ __launch_bounds__(256, 2)
void gemm_f16(const uint16_t* __restrict__ Ah_, int lda,
              const uint16_t* __restrict__ Wh, int ldw,
              const float* __restrict__ bias1,
              float* __restrict__ C, int N, int K)
{
    extern __shared__ char smc[];
    const uint32_t sb = smem_u32(smc);
    const int tid = threadIdx.x;
    const int wid = tid >> 5, lid = tid & 31;
    const int wm  = wid >> 2, wn = wid & 3;
    const int g   = lid >> 2, t  = lid & 3;
    const int m0  = blockIdx.y * 128;
    const int n0  = blockIdx.x * 128;

    float acc[4][4][4];
    #pragma unroll
    for (int a_ = 0; a_ < 4; a_++)
        #pragma unroll
        for (int b_ = 0; b_ < 4; b_++)
            #pragma unroll
            for (int e = 0; e < 4; e++) acc[a_][b_][e] = 0.f;

    const int r  = tid >> 1;
    const int jo = (tid & 1) * 32;
    const char* pAh = (const char*)(Ah_ + (size_t)(m0 + r) * lda) + jo;
    const char* pBh = (const char*)(Wh  + (size_t)(n0 + r) * ldw) + jo;
    const uint32_t dbase = sb + (uint32_t)(r * ROW_BY + jo);

    GEMM_MAINLOOP(K);

    #pragma unroll
    for (int mt = 0; mt < 4; mt++) {
        const int row  = m0 + wm * 64 + mt * 16 + g;
        const int row2 = row + 8;
        #pragma unroll
        for (int nt = 0; nt < 4; nt++) {
            const int col = n0 + wn * 32 + nt * 8 + 2 * t;
            float v0 = acc[mt][nt][0] + bias1[col];
            float v1 = acc[mt][nt][1] + bias1[col + 1];
            float v2 = acc[mt][nt][2] + bias1[col];
            float v3 = acc[mt][nt][3] + bias1[col + 1];
            *(float2*)(C + (size_t)row  * N + col) = make_float2(v0, v1);
            *(float2*)(C + (size_t)row2 * N + col) = make_float2(v2, v3);
        }
    }
}

// ===================== fused producer/consumer persistent kernel ============
// 256 CTAs x 256 thr, 2 CTA/SM, all co-resident.
// CTA < 128  : consumer — persistent LSTM recurrence on tile (m0,n0).
// CTA >= 128 : producer — streams Gin[t](same tile) = dh[t]@Wih^T + Gpool,
//              publishing per-(t,tile) ready flags. Producers never block.
__global__ __launch_bounds__(256, 2)
void fused_persist(const uint16_t* __restrict__ Whh,
                   const uint16_t* __restrict__ Wih,
                   const uint16_t* __restrict__ dh_h,
                   const float* __restrict__ Gpool,
                   float* __restrict__ Gin,
                   uint16_t* __restrict__ h_base,
                   float* __restrict__ outp)
{
    extern __shared__ char smc[];
    const uint32_t sb = smem_u32(smc);

    const int tid = threadIdx.x;
    const int wid = tid >> 5, lid = tid & 31;
    const int wm  = wid >> 2, wn = wid & 3;       // 2x4 warp grid
    const int g   = lid >> 2, t  = lid & 3;
    const bool producer = (blockIdx.x >= NTILE);
    const int tile = producer ? (blockIdx.x - NTILE) : blockIdx.x;
    const int m0  = (tile & 3) * 128;
    const int n0  = (tile >> 2) * 128;

    const int r  = tid >> 1;
    const int jo = (tid & 1) * 32;
    const uint32_t dbase = sb + (uint32_t)(r * ROW_BY + jo);

    if (producer) {
        // -------------------- producer --------------------
        // W_ih permuted rows have length 2*D_SZ (dh-half | pooled-half);
        // use stride 2*D_SZ, read only the first D_SZ columns. (R16 bug: D_SZ)
        const char* pBh = (const char*)(Wih + (size_t)(n0 + r) * (2 * D_SZ)) + jo;
        for (int ts = 1; ts < T_STEPS; ts++) {
            float acc[4][4][4];
            #pragma unroll
            for (int a_ = 0; a_ < 4; a_++)
                #pragma unroll
                for (int b_ = 0; b_ < 4; b_++)
                    #pragma unroll
                    for (int e = 0; e < 4; e++) acc[a_][b_][e] = 0.f;

            const char* pAh = (const char*)(dh_h + (size_t)(ts - 1) * B_SZ * D_SZ
                                            + (size_t)(m0 + r) * D_SZ) + jo;
            GEMM_MAINLOOP(D_SZ);

            float* C = Gin + (size_t)(ts - 1) * B_SZ * G4;
            #pragma unroll
            for (int mt = 0; mt < 4; mt++) {
                const int row  = m0 + wm * 64 + mt * 16 + g;
                const int row2 = row + 8;
                #pragma unroll
                for (int nt = 0; nt < 4; nt++) {
                    const int col = n0 + wn * 32 + nt * 8 + 2 * t;
                    float2 p0 = *(const float2*)(Gpool + (size_t)row  * G4 + col);
                    float2 p1 = *(const float2*)(Gpool + (size_t)row2 * G4 + col);
                    *(float2*)(C + (size_t)row  * G4 + col) =
                        make_float2(acc[mt][nt][0] + p0.x, acc[mt][nt][1] + p0.y);
                    *(float2*)(C + (size_t)row2 * G4 + col) =
                        make_float2(acc[mt][nt][2] + p1.x, acc[mt][nt][3] + p1.y);
                }
            }
            __syncthreads();
            if (tid == 0) {
                __threadfence();
                atomicExch(&g_gin_flag[ts * NTILE + tile], 1u);
            }
        }
        return;
    }

    // -------------------- consumer (persistent LSTM) --------------------
    const char* pBh = (const char*)(Whh + (size_t)(n0 + r) * H_SZ) + jo;

    float creg[4][4];
    #pragma unroll
    for (int mt = 0; mt < 4; mt++)
        #pragma unroll
        for (int nt = 0; nt < 4; nt++) creg[mt][nt] = 0.f;

    const bool even = ((t & 1) == 0);
    unsigned int bar_target = 0;

    for (int ts = 1; ts < T_STEPS; ts++) {
        float acc[4][4][4];
        #pragma unroll
        for (int a_ = 0; a_ < 4; a_++)
            #pragma unroll
            for (int b_ = 0; b_ < 4; b_++)
                #pragma unroll
                for (int e = 0; e < 4; e++) acc[a_][b_][e] = 0.f;

        if (ts >= 2) {
            const uint16_t* h_in = h_base + (size_t)((ts + 1) & 1) * BH;
            const char* pAh = (const char*)(h_in + (size_t)(m0 + r) * H_SZ) + jo;
            GEMM_MAINLOOP(H_SZ);
        }

        // wait for our Gin tile (produced by partner CTA)
        if (tid == 0) {
            unsigned int v;
            do {
                asm volatile("ld.global.acquire.gpu.u32 %0, [%1];"
                             : "=r"(v) : "l"(&g_gin_flag[ts * NTILE + tile]));
            } while (!v);
        }
        __syncthreads();

        // ---- LSTM epilogue (gate-permuted cols jj*4+G; tanh.approx) ----
        const float* add = Gin + (size_t)(ts - 1) * B_SZ * G4;
        uint16_t* h_out = h_base + (size_t)(ts & 1) * BH;
        #pragma unroll
        for (int mt = 0; mt < 4; mt++) {
            const int row  = m0 + wm * 64 + mt * 16 + g;
            const int row2 = row + 8;
            #pragma unroll
            for (int nt = 0; nt < 4; nt++) {
                const int col = n0 + wn * 32 + nt * 8 + 2 * t;
                float2 a0 = *(const float2*)(add + (size_t)row  * G4 + col);
                float2 a1 = *(const float2*)(add + (size_t)row2 * G4 + col);
                float v0 = acc[mt][nt][0] + a0.x;
                float v1 = acc[mt][nt][1] + a0.y;
                float v2 = acc[mt][nt][2] + a1.x;
                float v3 = acc[mt][nt][3] + a1.y;
                float q0 = __shfl_xor_sync(0xffffffffu, v0, 1);
                float q1 = __shfl_xor_sync(0xffffffffu, v1, 1);
                float q2 = __shfl_xor_sync(0xffffffffu, v2, 1);
                float q3 = __shfl_xor_sync(0xffffffffu, v3, 1);
                float gi = even ? v0 : q2;
                float gf = even ? v1 : q3;
                float gg = even ? q0 : v2;
                float go = even ? q1 : v3;
                const int rr = even ? row : row2;
                const int jj = (n0 + wn * 32 + nt * 8 + ((t & 2) << 1)) >> 2;
                float si = siga(gi), sf = siga(gf), so = siga(go);
                float tg = tanha(gg);
                float cn = sf * creg[mt][nt] + si * tg;
                creg[mt][nt] = cn;
                float hn = so * tanha(cn);
                h_out[(size_t)rr * H_SZ + jj] = (uint16_t)(fpack2(hn, 0.f) & 0xFFFFu);
                outp[(size_t)rr * T_STEPS * H_SZ + (size_t)ts * H_SZ + jj] = hn;
            }
        }

        // ---- grid barrier among 128 consumers (h visibility) ----
        if (ts < T_STEPS - 1) {
            bar_target += NTILE;
            __syncthreads();
            if (tid == 0) {
                __threadfence();
                atomicAdd(&g_bar_ctr, 1u);
                unsigned int v;
                do {
                    asm volatile("ld.global.acquire.gpu.u32 %0, [%1];"
                                 : "=r"(v) : "l"(&g_bar_ctr));
                } while (v < bar_target);
            }
            __syncthreads();
        }
    }
}

// ---------------- prep kernels ----------------------------------------------
__global__ void permute_w_f16(const float* __restrict__ W,
                              uint16_t* __restrict__ Wh, int K)
{
    const int rr = blockIdx.x;
    const int jj = rr >> 2, G = rr & 3;
    const float4* s = (const float4*)(W + (size_t)(G * H_SZ + jj) * K);
    uint2* d = (uint2*)(Wh + (size_t)rr * K);
    for (int k = threadIdx.x; k < K / 4; k += blockDim.x) {
        float4 v = s[k];
        uint2 o;
        o.x = fpack2(v.x, v.y);
        o.y = fpack2(v.z, v.w);
        d[k] = o;
    }
}

__global__ void permute_bias(const float* __restrict__ b_ih,
                             const float* __restrict__ b_hh,
                             float* __restrict__ bp)
{
    int rr = blockIdx.x * blockDim.x + threadIdx.x;
    int jj = rr >> 2, G = rr & 3;
    bp[rr] = b_ih[G * H_SZ + jj] + b_hh[G * H_SZ + jj];
}

__global__ void conv_dh(const float* __restrict__ src, uint16_t* __restrict__ dst)
{
    size_t i = (size_t)blockIdx.x * blockDim.x + threadIdx.x;
    float4 v = ((const float4*)src)[i];
    uint2 o;
    o.x = fpack2(v.x, v.y);
    o.y = fpack2(v.z, v.w);
    ((uint2*)dst)[i] = o;
}

__global__ void pooled_kernel(const float* __restrict__ dh,
                              const int* __restrict__ cap,
                              uint16_t* __restrict__ ph)
{
    int b  = blockIdx.x;
    int d4 = threadIdx.x;
    float4 acc = make_float4(0.f, 0.f, 0.f, 0.f);
    float len = 0.f;
    #pragma unroll
    for (int t = 0; t < T_STEPS; t++) {
        int v = cap[t * B_SZ + b];
        float m = (v != 0 && v != 2) ? 1.f : 0.f;
        len += m;
        float4 x = *(const float4*)(dh + (size_t)t * B_SZ * D_SZ + (size_t)b * D_SZ + d4 * 4);
        acc.x += m * x.x; acc.y += m * x.y; acc.z += m * x.z; acc.w += m * x.w;
    }
    float inv = 1.f / len;
    uint2 o;
    o.x = fpack2(acc.x * inv, acc.y * inv);
    o.y = fpack2(acc.z * inv, acc.w * inv);
    ((uint2*)(ph + (size_t)b * D_SZ))[d4] = o;
}

// zero out[:,0,:]; reset grid-barrier counter + Gin ready flags
__global__ void init_kernel(float* __restrict__ out)
{
    int idx = blockIdx.x * blockDim.x + threadIdx.x;   // over B*H
    int b = idx >> 10;
    int j = idx & 1023;
    out[(size_t)b * T_STEPS * H_SZ + j] = 0.f;
    if (idx < T_STEPS * NTILE) g_gin_flag[idx] = 0u;
    if (idx == 0) g_bar_ctr = 0u;
}

// ---------------------------------------------------------------------------
extern "C" void kernel_launch(void* const* d_in, const int* in_sizes, int n_in,
                              void* d_out, int out_size)
{
    const float* dh    = (const float*)d_in[0];      // [T,1,B,D] == [T,B,D]
    const int*   cap   = (const int*)d_in[2];        // [T,B] int32
    const float* W_ih  = (const float*)d_in[3];      // [4H, 2D]
    const float* W_hh  = (const float*)d_in[4];      // [4H, H]
    const float* b_ih  = (const float*)d_in[5];      // [4H]
    const float* b_hh  = (const float*)d_in[6];      // [4H]
    float*       out   = (float*)d_out;              // [B, T, H]

    float *Gpool, *Gin, *biasp;
    uint16_t *wih_h, *whh_h, *dh_h, *pl_h, *h_h;
    cudaGetSymbolAddress((void**)&Gpool, g_Gpool);
    cudaGetSymbolAddress((void**)&Gin,   g_Gin);
    cudaGetSymbolAddress((void**)&biasp, g_bias_p);
    cudaGetSymbolAddress((void**)&wih_h, g_wih_h);
    cudaGetSymbolAddress((void**)&whh_h, g_whh_h);
    cudaGetSymbolAddress((void**)&dh_h,  g_dh_h);
    cudaGetSymbolAddress((void**)&pl_h,  g_pl_h);
    cudaGetSymbolAddress((void**)&h_h,   g_h_h);

    cudaFuncSetAttribute(gemm_f16, cudaFuncAttributeMaxDynamicSharedMemorySize, SMEM_B);
    cudaFuncSetAttribute(fused_persist, cudaFuncAttributeMaxDynamicSharedMemorySize, SMEM_B);

    // 0) prep: permute weights -> fp16, bias; convert dh[1:]; pooled mean
    permute_w_f16<<<G4, 256>>>(W_ih, wih_h, 2 * D_SZ);
    permute_w_f16<<<G4, 256>>>(W_hh, whh_h, H_SZ);
    permute_bias<<<G4 / 256, 256>>>(b_ih, b_hh, biasp);
    conv_dh<<<((T_STEPS - 1) * B_SZ * D_SZ / 4) / 256, 256>>>(
        dh + (size_t)B_SZ * D_SZ, dh_h);
    pooled_kernel<<<B_SZ, 256>>>(dh, cap, pl_h);
    init_kernel<<<(B_SZ * H_SZ) / 256, 256>>>(out);

    // 1) Gpool = pooled @ Wihp[:, D:]^T + bias_p
    gemm_f16<<<dim3(G4 / 128, B_SZ / 128), 256, SMEM_B>>>(
        pl_h, D_SZ, wih_h + D_SZ, 2 * D_SZ, biasp, Gpool, G4, D_SZ);

    // 2) fused: 128 producer CTAs stream Gin[t]; 128 consumer CTAs run the
    //    persistent recurrence, overlapped on the same SMs.
    fused_persist<<<2 * NTILE, 256, SMEM_B>>>(
        whh_h, wih_h, dh_h, Gpool, Gin, h_h, out);
}